// round 4
// baseline (speedup 1.0000x reference)
#include <cuda_runtime.h>
#include <cuda_fp16.h>
#include <math.h>

// ---------------- problem-size caps (compile-time scratch) ----------------
#define NMAX 100000
#define EMAX 1700000   // E + N self loops

// ---------------- device scratch (no allocations allowed) -----------------
__device__ __half g_h1[NMAX * 128];   // layer1 features, fp16 message table [N, 2*64]
__device__ float  g_hf[NMAX * 64];    // layer1 output after head-mean+bias+elu (fp32)
__device__ __half g_h2[NMAX * 64];    // layer2 features, fp16 message table [N, 2*32]
__device__ float2 g_as1[NMAX], g_ad1[NMAX];
__device__ float2 g_as2[NMAX], g_ad2[NMAX];
__device__ int    g_counts[NMAX];
__device__ int    g_offsets[NMAX + 1];
__device__ int    g_cursor[NMAX];
__device__ int    g_adj[EMAX];
__device__ int    g_bsums[128];

__device__ __forceinline__ float lrelu(float x) { return x > 0.f ? x : 0.2f * x; }

// ---- packed f32x2 helpers (Blackwell FFMA2 path, PTX-only) ----
__device__ __forceinline__ unsigned long long pack2(float lo, float hi) {
    unsigned long long r;
    asm("mov.b64 %0, {%1, %2};" : "=l"(r) : "f"(lo), "f"(hi));
    return r;
}
__device__ __forceinline__ void ffma2(unsigned long long& d, unsigned long long a,
                                      unsigned long long b) {
    asm("fma.rn.f32x2 %0, %1, %2, %0;" : "+l"(d) : "l"(a), "l"(b));
}
__device__ __forceinline__ float2 unpack2(unsigned long long v) {
    float2 r;
    asm("mov.b64 {%0, %1}, %2;" : "=f"(r.x), "=f"(r.y) : "l"(v));
    return r;
}

// ---------------- CSR build ----------------
__global__ void zero_counts_kernel(int* counts, int n) {
    int i = blockIdx.x * blockDim.x + threadIdx.x;
    if (i < n) counts[i] = 0;
}

__global__ void count_kernel(const int* __restrict__ ei, int E, int N, int* counts) {
    int e = blockIdx.x * blockDim.x + threadIdx.x;
    int tot = E + N;
    if (e >= tot) return;
    int dst = (e < E) ? ei[E + e] : (e - E);
    atomicAdd(&counts[dst], 1);
}

__global__ void scan1_kernel(const int* __restrict__ counts, int* offsets, int* bsums, int n) {
    __shared__ int s[1024];
    int tid = threadIdx.x;
    int i = blockIdx.x * 1024 + tid;
    int v = (i < n) ? counts[i] : 0;
    s[tid] = v;
    __syncthreads();
#pragma unroll
    for (int d = 1; d < 1024; d <<= 1) {
        int t = (tid >= d) ? s[tid - d] : 0;
        __syncthreads();
        s[tid] += t;
        __syncthreads();
    }
    if (i < n) offsets[i + 1] = s[tid];
    if (tid == 1023) bsums[blockIdx.x] = s[tid];
}

__global__ void scan2_kernel(int* bsums, int nb) {
    __shared__ int s[128];
    int t = threadIdx.x;
    int v = (t < nb) ? bsums[t] : 0;
    s[t] = v;
    __syncthreads();
#pragma unroll
    for (int d = 1; d < 128; d <<= 1) {
        int x = (t >= d) ? s[t - d] : 0;
        __syncthreads();
        s[t] += x;
        __syncthreads();
    }
    if (t < nb) bsums[t] = s[t] - v;  // exclusive block prefix
}

__global__ void scan3_kernel(int* offsets, const int* __restrict__ bsums,
                             const int* __restrict__ counts, int* cursor, int n) {
    int i = blockIdx.x * blockDim.x + threadIdx.x;
    if (i == 0) offsets[0] = 0;
    if (i < n) {
        int o = offsets[i + 1] + bsums[i >> 10];
        offsets[i + 1] = o;
        cursor[i] = o - counts[i];
    }
}

__global__ void scatter_kernel(const int* __restrict__ ei, int E, int N,
                               int* cursor, int* __restrict__ adj) {
    int e = blockIdx.x * blockDim.x + threadIdx.x;
    int tot = E + N;
    if (e >= tot) return;
    int src, dst;
    if (e < E) { src = ei[e]; dst = ei[E + e]; }
    else       { src = e - E; dst = e - E; }
    int pos = atomicAdd(&cursor[dst], 1);
    adj[pos] = src;
}

// ---------------- GEMM (FFMA2) + fp16 store + fused attention coeffs ----------
// H[n, M](fp16) = A[n, K] @ W[K, M];  as/ad[n,head] = <row, att_{src,dst}> per head.
// 256 threads; TXN = M/TN column-threads, TYN = 256/TXN row-threads, BM = TYN*TM.
// All smem loads of one k4 step batched up front (MLP ~12) before the FFMA2 block.
template <int K, int M, int BM, int TM, int TN>
__global__ __launch_bounds__(256, 2) void gemm_attn_kernel(
    const float* __restrict__ A, const float* __restrict__ W,
    const float* __restrict__ att_src, const float* __restrict__ att_dst,
    __half* __restrict__ Hh, float* __restrict__ as, float* __restrict__ ad, int n) {
    extern __shared__ float smem[];
    float* Ws = smem;            // K*M
    float* As = smem + K * M;    // BM*K  (row-major)
    const int TXN = M / TN;
    int tid = threadIdx.x;

    const float4* W4 = (const float4*)W;
    float4* Ws4 = (float4*)Ws;
#pragma unroll 4
    for (int i = tid; i < K * M / 4; i += 256) Ws4[i] = W4[i];

    int row0 = blockIdx.x * BM;
    float4* As4 = (float4*)As;
    const float4* A4 = (const float4*)A;
#pragma unroll 4
    for (int i = tid; i < BM * K / 4; i += 256) {
        int r = i / (K / 4), kk = i % (K / 4);
        int row = row0 + r;
        As4[i] = (row < n) ? A4[(size_t)row * (K / 4) + kk] : make_float4(0.f, 0.f, 0.f, 0.f);
    }
    __syncthreads();

    int ty = tid / TXN, tx = tid % TXN;
    int c0 = tx * TN;
    unsigned long long acc2[TM][TN / 2];
#pragma unroll
    for (int i = 0; i < TM; i++)
#pragma unroll
        for (int j = 0; j < TN / 2; j++) acc2[i][j] = 0ull;

#pragma unroll 1
    for (int k4 = 0; k4 < K; k4 += 4) {
        // batched loads: TM a-vectors + 4*TN/4 w-vectors, all independent
        float4 a4[TM];
#pragma unroll
        for (int i = 0; i < TM; i++)
            a4[i] = *(const float4*)&As[(ty * TM + i) * K + k4];
        unsigned long long w2[4][TN / 2];
#pragma unroll
        for (int kk = 0; kk < 4; kk++)
#pragma unroll
            for (int j = 0; j < TN / 4; j++) {
                float4 wv = *(const float4*)&Ws[(k4 + kk) * M + c0 + 4 * j];
                w2[kk][2 * j]     = pack2(wv.x, wv.y);
                w2[kk][2 * j + 1] = pack2(wv.z, wv.w);
            }
#pragma unroll
        for (int kk = 0; kk < 4; kk++)
#pragma unroll
            for (int i = 0; i < TM; i++) {
                float av = ((const float*)&a4[i])[kk];
                unsigned long long a2 = pack2(av, av);
#pragma unroll
                for (int j = 0; j < TN / 2; j++) ffma2(acc2[i][j], a2, w2[kk][j]);
            }
    }

    // unpack accumulators
    float acc[TM][TN];
#pragma unroll
    for (int i = 0; i < TM; i++)
#pragma unroll
        for (int j = 0; j < TN / 2; j++) {
            float2 f = unpack2(acc2[i][j]);
            acc[i][2 * j] = f.x;
            acc[i][2 * j + 1] = f.y;
        }

    // ---- fp16 feature store ----
#pragma unroll
    for (int i = 0; i < TM; i++) {
        int row = row0 + ty * TM + i;
        if (row < n) {
            unsigned u[TN / 2];
#pragma unroll
            for (int j = 0; j < TN / 2; j++) {
                __half2 hp = __floats2half2_rn(acc[i][2 * j], acc[i][2 * j + 1]);
                u[j] = *(unsigned*)&hp;
            }
            __half* dst = Hh + (size_t)row * M + c0;
            if (TN == 8) *(uint4*)dst = make_uint4(u[0], u[1], u[2], u[3]);
            else         *(uint2*)dst = make_uint2(u[0], u[1]);
        }
    }

    // ---- fused attention coefficients (fp32 exact) ----
    float atts[TN], attd[TN];
#pragma unroll
    for (int j = 0; j < TN; j++) { atts[j] = att_src[c0 + j]; attd[j] = att_dst[c0 + j]; }
    float ps[TM], pd[TM];
#pragma unroll
    for (int i = 0; i < TM; i++) {
        float s = 0.f, d = 0.f;
#pragma unroll
        for (int j = 0; j < TN; j++) {
            s = fmaf(acc[i][j], atts[j], s);
            d = fmaf(acc[i][j], attd[j], d);
        }
        ps[i] = s; pd[i] = d;
    }
    // reduce across the TXN/2 lanes of one head (xor flips tx bits only)
#pragma unroll
    for (int off = 1; off < TXN / 2; off <<= 1) {
#pragma unroll
        for (int i = 0; i < TM; i++) {
            ps[i] += __shfl_xor_sync(0xffffffffu, ps[i], off);
            pd[i] += __shfl_xor_sync(0xffffffffu, pd[i], off);
        }
    }
    int head = tx / (TXN / 2);
    if ((tx % (TXN / 2)) == 0) {
#pragma unroll
        for (int i = 0; i < TM; i++) {
            int row = row0 + ty * TM + i;
            if (row < n) {
                as[2 * row + head] = ps[i];
                ad[2 * row + head] = pd[i];
            }
        }
    }
}

// -------------- per-destination softmax + aggregate (one warp / node) ----------
template <int C, bool ELU>
__global__ void aggregate_kernel(const __half* __restrict__ h,
                                 const float2* __restrict__ as,
                                 const float2* __restrict__ ad,
                                 const int* __restrict__ offsets,
                                 const int* __restrict__ adj,
                                 const float* __restrict__ bias,
                                 float* __restrict__ out, int n) {
    const int VEC = 2 * C / 32;   // halfs per lane: 4 for C=64, 2 for C=32
    int warp = (blockIdx.x * blockDim.x + threadIdx.x) >> 5;
    int lane = threadIdx.x & 31;
    if (warp >= n) return;

    int beg = offsets[warp], end = offsets[warp + 1];
    float2 adv = ad[warp];
    bool head0 = lane < 16;

    float acc[VEC];
#pragma unroll
    for (int k = 0; k < VEC; k++) acc[k] = 0.f;
    float d0 = 0.f, d1 = 0.f;
    const __half* hlane = h + lane * VEC;

    for (int chunk = beg; chunk < end; chunk += 32) {
        int cn = end - chunk;
        if (cn > 32) cn = 32;
        int s = 0; float w0 = 0.f, w1 = 0.f;
        if (lane < cn) {
            s = adj[chunk + lane];
            float2 a = as[s];
            w0 = __expf(lrelu(a.x + adv.x));
            w1 = __expf(lrelu(a.y + adv.y));
        }
        d0 += w0; d1 += w1;

        int t = 0;
        for (; t + 2 <= cn; t += 2) {
            int s0 = __shfl_sync(0xffffffffu, s, t);
            int s1 = __shfl_sync(0xffffffffu, s, t + 1);
            float wa0 = __shfl_sync(0xffffffffu, w0, t);
            float wb0 = __shfl_sync(0xffffffffu, w1, t);
            float wa1 = __shfl_sync(0xffffffffu, w0, t + 1);
            float wb1 = __shfl_sync(0xffffffffu, w1, t + 1);
            float we0 = head0 ? wa0 : wb0;
            float we1 = head0 ? wa1 : wb1;
            if (VEC == 4) {
                uint2 r0 = *(const uint2*)(hlane + (size_t)s0 * 2 * C);
                uint2 r1 = *(const uint2*)(hlane + (size_t)s1 * 2 * C);
                float2 f0 = __half22float2(*(__half2*)&r0.x);
                float2 f1 = __half22float2(*(__half2*)&r0.y);
                float2 g0 = __half22float2(*(__half2*)&r1.x);
                float2 g1 = __half22float2(*(__half2*)&r1.y);
                acc[0] = fmaf(we0, f0.x, acc[0]); acc[1] = fmaf(we0, f0.y, acc[1]);
                acc[2] = fmaf(we0, f1.x, acc[2]); acc[3] = fmaf(we0, f1.y, acc[3]);
                acc[0] = fmaf(we1, g0.x, acc[0]); acc[1] = fmaf(we1, g0.y, acc[1]);
                acc[2] = fmaf(we1, g1.x, acc[2]); acc[3] = fmaf(we1, g1.y, acc[3]);
            } else {
                unsigned r0 = *(const unsigned*)(hlane + (size_t)s0 * 2 * C);
                unsigned r1 = *(const unsigned*)(hlane + (size_t)s1 * 2 * C);
                float2 f0 = __half22float2(*(__half2*)&r0);
                float2 g0 = __half22float2(*(__half2*)&r1);
                acc[0] = fmaf(we0, f0.x, acc[0]); acc[1] = fmaf(we0, f0.y, acc[1]);
                acc[0] = fmaf(we1, g0.x, acc[0]); acc[1] = fmaf(we1, g0.y, acc[1]);
            }
        }
        if (t < cn) {
            int s0 = __shfl_sync(0xffffffffu, s, t);
            float wa0 = __shfl_sync(0xffffffffu, w0, t);
            float wb0 = __shfl_sync(0xffffffffu, w1, t);
            float we0 = head0 ? wa0 : wb0;
            if (VEC == 4) {
                uint2 r0 = *(const uint2*)(hlane + (size_t)s0 * 2 * C);
                float2 f0 = __half22float2(*(__half2*)&r0.x);
                float2 f1 = __half22float2(*(__half2*)&r0.y);
                acc[0] = fmaf(we0, f0.x, acc[0]); acc[1] = fmaf(we0, f0.y, acc[1]);
                acc[2] = fmaf(we0, f1.x, acc[2]); acc[3] = fmaf(we0, f1.y, acc[3]);
            } else {
                unsigned r0 = *(const unsigned*)(hlane + (size_t)s0 * 2 * C);
                float2 f0 = __half22float2(*(__half2*)&r0);
                acc[0] = fmaf(we0, f0.x, acc[0]); acc[1] = fmaf(we0, f0.y, acc[1]);
            }
        }
    }

#pragma unroll
    for (int off = 16; off >= 1; off >>= 1) {
        d0 += __shfl_xor_sync(0xffffffffu, d0, off);
        d1 += __shfl_xor_sync(0xffffffffu, d1, off);
    }
    float dm = (head0 ? d0 : d1) + 1e-16f;

    float res[VEC];
#pragma unroll
    for (int k = 0; k < VEC; k++) {
        float x = acc[k] / dm;
        float y = __shfl_xor_sync(0xffffffffu, x, 16);  // partner head value
        res[k] = 0.5f * (x + y);
    }
    if (head0) {
        int c0 = lane * VEC;
#pragma unroll
        for (int k = 0; k < VEC; k++) {
            float v = res[k] + bias[c0 + k];
            if (ELU) v = v > 0.f ? v : expm1f(v);
            res[k] = v;
        }
        float* op = out + (size_t)warp * C + c0;
        if (VEC == 4) *(float4*)op = make_float4(res[0], res[1], res[2], res[3]);
        else          *(float2*)op = make_float2(res[0], res[1]);
    }
}

// ---------------------------- launch ----------------------------
extern "C" void kernel_launch(void* const* d_in, const int* in_sizes, int n_in,
                              void* d_out, int out_size) {
    const float* x    = (const float*)d_in[0];
    const int*   ei   = (const int*)d_in[1];
    const float* W1   = (const float*)d_in[2];
    const float* as1w = (const float*)d_in[3];
    const float* ad1w = (const float*)d_in[4];
    const float* b1   = (const float*)d_in[5];
    const float* W2   = (const float*)d_in[6];
    const float* as2w = (const float*)d_in[7];
    const float* ad2w = (const float*)d_in[8];
    const float* b2   = (const float*)d_in[9];
    float* out = (float*)d_out;

    int N = in_sizes[0] / 128;
    int E = in_sizes[1] / 2;
    if (N > NMAX) N = NMAX;
    int Etot = E + N;

    __half *h1, *h2;
    float *hf;
    float2 *pas1, *pad1, *pas2, *pad2;
    int *counts, *offsets, *cursor, *adj, *bsums;
    cudaGetSymbolAddress((void**)&h1,     g_h1);
    cudaGetSymbolAddress((void**)&hf,     g_hf);
    cudaGetSymbolAddress((void**)&h2,     g_h2);
    cudaGetSymbolAddress((void**)&pas1,   g_as1);
    cudaGetSymbolAddress((void**)&pad1,   g_ad1);
    cudaGetSymbolAddress((void**)&pas2,   g_as2);
    cudaGetSymbolAddress((void**)&pad2,   g_ad2);
    cudaGetSymbolAddress((void**)&counts, g_counts);
    cudaGetSymbolAddress((void**)&offsets,g_offsets);
    cudaGetSymbolAddress((void**)&cursor, g_cursor);
    cudaGetSymbolAddress((void**)&adj,    g_adj);
    cudaGetSymbolAddress((void**)&bsums,  g_bsums);

    // GEMM1: BM=64, TM=4, TN=8 -> smem 96 KB -> 2 CTAs/SM (16 warps)
    const int SM1 = (128 * 128 + 64 * 128) * 4;   // 96 KB
    // GEMM2: BM=128, TM=4, TN=8 -> smem 48 KB -> 3-4 CTAs/SM
    const int SM2 = (64 * 64 + 128 * 64) * 4;     // 48 KB
    cudaFuncSetAttribute(gemm_attn_kernel<128, 128, 64, 4, 8>,
                         cudaFuncAttributeMaxDynamicSharedMemorySize, SM1);
    cudaFuncSetAttribute(gemm_attn_kernel<64, 64, 128, 4, 8>,
                         cudaFuncAttributeMaxDynamicSharedMemorySize, SM2);

    // ---- CSR build interleaved with layer-1 GEMM (GEMM at capture slot #3) ----
    zero_counts_kernel<<<(N + 255) / 256, 256>>>(counts, N);                     // 0
    count_kernel<<<(Etot + 255) / 256, 256>>>(ei, E, N, counts);                 // 1
    int nb = (N + 1023) / 1024;
    scan1_kernel<<<nb, 1024>>>(counts, offsets, bsums, N);                       // 2
    gemm_attn_kernel<128, 128, 64, 4, 8><<<(N + 63) / 64, 256, SM1>>>(           // 3
        x, W1, as1w, ad1w, h1, (float*)pas1, (float*)pad1, N);
    scan2_kernel<<<1, 128>>>(bsums, nb);                                         // 4
    scan3_kernel<<<(N + 255) / 256, 256>>>(offsets, bsums, counts, cursor, N);   // 5
    scatter_kernel<<<(Etot + 255) / 256, 256>>>(ei, E, N, cursor, adj);          // 6

    int warpGrid = (N * 32 + 255) / 256;
    aggregate_kernel<64, true><<<warpGrid, 256>>>(h1, pas1, pad1, offsets, adj, b1, hf, N);   // 7

    gemm_attn_kernel<64, 64, 128, 4, 8><<<(N + 127) / 128, 256, SM2>>>(          // 8
        hf, W2, as2w, ad2w, h2, (float*)pas2, (float*)pad2, N);
    aggregate_kernel<32, false><<<warpGrid, 256>>>(h2, pas2, pad2, offsets, adj, b2, out, N); // 9
}

// round 5
// speedup vs baseline: 1.1352x; 1.1352x over previous
#include <cuda_runtime.h>
#include <cuda_fp16.h>
#include <math.h>

// ---------------- problem-size caps (compile-time scratch) ----------------
#define NMAX 100000
#define EMAX 1700000   // E + N self loops

// ---------------- device scratch (no allocations allowed) -----------------
__device__ __half g_h1[NMAX * 128];   // layer1 features, fp16 message table [N, 2*64]
__device__ float  g_hf[NMAX * 64];    // layer1 output after head-mean+bias+elu (fp32)
__device__ __half g_h2[NMAX * 64];    // layer2 features, fp16 message table [N, 2*32]
__device__ float2 g_as1[NMAX], g_ad1[NMAX];
__device__ float2 g_as2[NMAX], g_ad2[NMAX];
__device__ int    g_counts[NMAX];
__device__ int    g_offsets[NMAX + 1];
__device__ int    g_cursor[NMAX];
__device__ int    g_adj[EMAX];
__device__ int    g_bsums[128];

__device__ __forceinline__ float lrelu(float x) { return x > 0.f ? x : 0.2f * x; }

// ---- packed f32x2 helpers (Blackwell FFMA2 path, PTX-only) ----
__device__ __forceinline__ unsigned long long pack2(float lo, float hi) {
    unsigned long long r;
    asm("mov.b64 %0, {%1, %2};" : "=l"(r) : "f"(lo), "f"(hi));
    return r;
}
__device__ __forceinline__ void ffma2(unsigned long long& d, unsigned long long a,
                                      unsigned long long b) {
    asm("fma.rn.f32x2 %0, %1, %2, %0;" : "+l"(d) : "l"(a), "l"(b));
}
__device__ __forceinline__ float2 unpack2(unsigned long long v) {
    float2 r;
    asm("mov.b64 {%0, %1}, %2;" : "=f"(r.x), "=f"(r.y) : "l"(v));
    return r;
}

// ---------------- CSR build ----------------
__global__ void zero_counts_kernel(int* counts, int n) {
    int i = blockIdx.x * blockDim.x + threadIdx.x;
    if (i < n) counts[i] = 0;
}

__global__ void count_kernel(const int* __restrict__ ei, int E, int N, int* counts) {
    int e = blockIdx.x * blockDim.x + threadIdx.x;
    int tot = E + N;
    if (e >= tot) return;
    int dst = (e < E) ? ei[E + e] : (e - E);
    atomicAdd(&counts[dst], 1);
}

__global__ void scan1_kernel(const int* __restrict__ counts, int* offsets, int* bsums, int n) {
    __shared__ int s[1024];
    int tid = threadIdx.x;
    int i = blockIdx.x * 1024 + tid;
    int v = (i < n) ? counts[i] : 0;
    s[tid] = v;
    __syncthreads();
#pragma unroll
    for (int d = 1; d < 1024; d <<= 1) {
        int t = (tid >= d) ? s[tid - d] : 0;
        __syncthreads();
        s[tid] += t;
        __syncthreads();
    }
    if (i < n) offsets[i + 1] = s[tid];
    if (tid == 1023) bsums[blockIdx.x] = s[tid];
}

__global__ void scan2_kernel(int* bsums, int nb) {
    __shared__ int s[128];
    int t = threadIdx.x;
    int v = (t < nb) ? bsums[t] : 0;
    s[t] = v;
    __syncthreads();
#pragma unroll
    for (int d = 1; d < 128; d <<= 1) {
        int x = (t >= d) ? s[t - d] : 0;
        __syncthreads();
        s[t] += x;
        __syncthreads();
    }
    if (t < nb) bsums[t] = s[t] - v;  // exclusive block prefix
}

__global__ void scan3_kernel(int* offsets, const int* __restrict__ bsums,
                             const int* __restrict__ counts, int* cursor, int n) {
    int i = blockIdx.x * blockDim.x + threadIdx.x;
    if (i == 0) offsets[0] = 0;
    if (i < n) {
        int o = offsets[i + 1] + bsums[i >> 10];
        offsets[i + 1] = o;
        cursor[i] = o - counts[i];
    }
}

__global__ void scatter_kernel(const int* __restrict__ ei, int E, int N,
                               int* cursor, int* __restrict__ adj) {
    int e = blockIdx.x * blockDim.x + threadIdx.x;
    int tot = E + N;
    if (e >= tot) return;
    int src, dst;
    if (e < E) { src = ei[e]; dst = ei[E + e]; }
    else       { src = e - E; dst = e - E; }
    int pos = atomicAdd(&cursor[dst], 1);
    adj[pos] = src;
}

// ---------------- GEMM (FFMA2) + fp16 store + fused attention coeffs ----------
// H[n, M](fp16) = A[n, K] @ W[K, M];  as/ad[n,head] = <row, att_{src,dst}>.
// 256 threads; TXN = M/TN column-threads, TYN = 256/TXN, BM = TYN*TM.
// W fully smem-resident; A staged in K-chunks of KC (smem = K*M*4 + BM*KC*4).
template <int K, int M, int KC, int TM, int TN>
__global__ __launch_bounds__(256, 2) void gemm_attn_kernel(
    const float* __restrict__ A, const float* __restrict__ W,
    const float* __restrict__ att_src, const float* __restrict__ att_dst,
    __half* __restrict__ Hh, float* __restrict__ as, float* __restrict__ ad, int n) {
    const int TXN = M / TN;
    const int TYN = 256 / TXN;
    const int BM = TYN * TM;
    extern __shared__ float smem[];
    float* Ws = smem;            // K*M
    float* As = smem + K * M;    // BM*KC  (row-major, KC-wide rows)
    int tid = threadIdx.x;

    const float4* W4 = (const float4*)W;
    float4* Ws4 = (float4*)Ws;
#pragma unroll 4
    for (int i = tid; i < K * M / 4; i += 256) Ws4[i] = W4[i];

    int row0 = blockIdx.x * BM;
    float4* As4 = (float4*)As;
    const float4* A4 = (const float4*)A;

    int ty = tid / TXN, tx = tid % TXN;
    int c0 = tx * TN;
    unsigned long long acc2[TM][TN / 2];
#pragma unroll
    for (int i = 0; i < TM; i++)
#pragma unroll
        for (int j = 0; j < TN / 2; j++) acc2[i][j] = 0ull;

#pragma unroll 1
    for (int kc0 = 0; kc0 < K; kc0 += KC) {
        __syncthreads();   // also covers Ws readiness on first iter
        // stage A chunk [BM, KC]
#pragma unroll 4
        for (int i = tid; i < BM * KC / 4; i += 256) {
            int r = i / (KC / 4), kk = i % (KC / 4);
            int row = row0 + r;
            As4[i] = (row < n) ? A4[(size_t)row * (K / 4) + kc0 / 4 + kk]
                               : make_float4(0.f, 0.f, 0.f, 0.f);
        }
        __syncthreads();

#pragma unroll 1
        for (int k4 = 0; k4 < KC; k4 += 4) {
            float4 a4[TM];
#pragma unroll
            for (int i = 0; i < TM; i++)
                a4[i] = *(const float4*)&As[(ty * TM + i) * KC + k4];
#pragma unroll
            for (int kk = 0; kk < 4; kk++) {
                unsigned long long w2[TN / 2];
#pragma unroll
                for (int j = 0; j < TN / 4; j++) {
                    float4 wv = *(const float4*)&Ws[(kc0 + k4 + kk) * M + c0 + 4 * j];
                    w2[2 * j]     = pack2(wv.x, wv.y);
                    w2[2 * j + 1] = pack2(wv.z, wv.w);
                }
#pragma unroll
                for (int i = 0; i < TM; i++) {
                    float av = ((const float*)&a4[i])[kk];
                    unsigned long long a2 = pack2(av, av);
#pragma unroll
                    for (int j = 0; j < TN / 2; j++) ffma2(acc2[i][j], a2, w2[j]);
                }
            }
        }
    }

    // unpack accumulators
    float acc[TM][TN];
#pragma unroll
    for (int i = 0; i < TM; i++)
#pragma unroll
        for (int j = 0; j < TN / 2; j++) {
            float2 f = unpack2(acc2[i][j]);
            acc[i][2 * j] = f.x;
            acc[i][2 * j + 1] = f.y;
        }

    // ---- fp16 feature store ----
#pragma unroll
    for (int i = 0; i < TM; i++) {
        int row = row0 + ty * TM + i;
        if (row < n) {
            unsigned u[TN / 2];
#pragma unroll
            for (int j = 0; j < TN / 2; j++) {
                __half2 hp = __floats2half2_rn(acc[i][2 * j], acc[i][2 * j + 1]);
                u[j] = *(unsigned*)&hp;
            }
            __half* dst = Hh + (size_t)row * M + c0;
            if (TN == 8) *(uint4*)dst = make_uint4(u[0], u[1], u[2], u[3]);
            else         *(uint2*)dst = make_uint2(u[0], u[1]);
        }
    }

    // ---- fused attention coefficients (fp32 exact) ----
    float atts[TN], attd[TN];
#pragma unroll
    for (int j = 0; j < TN; j++) { atts[j] = att_src[c0 + j]; attd[j] = att_dst[c0 + j]; }
    float ps[TM], pd[TM];
#pragma unroll
    for (int i = 0; i < TM; i++) {
        float s = 0.f, d = 0.f;
#pragma unroll
        for (int j = 0; j < TN; j++) {
            s = fmaf(acc[i][j], atts[j], s);
            d = fmaf(acc[i][j], attd[j], d);
        }
        ps[i] = s; pd[i] = d;
    }
    // reduce across the TXN/2 lanes of one head (xor flips tx bits only)
#pragma unroll
    for (int off = 1; off < TXN / 2; off <<= 1) {
#pragma unroll
        for (int i = 0; i < TM; i++) {
            ps[i] += __shfl_xor_sync(0xffffffffu, ps[i], off);
            pd[i] += __shfl_xor_sync(0xffffffffu, pd[i], off);
        }
    }
    int head = tx / (TXN / 2);
    if ((tx % (TXN / 2)) == 0) {
#pragma unroll
        for (int i = 0; i < TM; i++) {
            int row = row0 + ty * TM + i;
            if (row < n) {
                as[2 * row + head] = ps[i];
                ad[2 * row + head] = pd[i];
            }
        }
    }
}

// -------------- per-destination softmax + aggregate (one warp / node) ----------
template <int C, bool ELU>
__global__ void aggregate_kernel(const __half* __restrict__ h,
                                 const float2* __restrict__ as,
                                 const float2* __restrict__ ad,
                                 const int* __restrict__ offsets,
                                 const int* __restrict__ adj,
                                 const float* __restrict__ bias,
                                 float* __restrict__ out, int n) {
    const int VEC = 2 * C / 32;   // halfs per lane: 4 for C=64, 2 for C=32
    int warp = (blockIdx.x * blockDim.x + threadIdx.x) >> 5;
    int lane = threadIdx.x & 31;
    if (warp >= n) return;

    int beg = offsets[warp], end = offsets[warp + 1];
    float2 adv = ad[warp];
    bool head0 = lane < 16;

    float acc[VEC];
#pragma unroll
    for (int k = 0; k < VEC; k++) acc[k] = 0.f;
    float d0 = 0.f, d1 = 0.f;
    const __half* hlane = h + lane * VEC;

    for (int chunk = beg; chunk < end; chunk += 32) {
        int cn = end - chunk;
        if (cn > 32) cn = 32;
        int s = 0; float w0 = 0.f, w1 = 0.f;
        if (lane < cn) {
            s = adj[chunk + lane];
            float2 a = as[s];
            w0 = __expf(lrelu(a.x + adv.x));
            w1 = __expf(lrelu(a.y + adv.y));
        }
        d0 += w0; d1 += w1;

        int t = 0;
        for (; t + 2 <= cn; t += 2) {
            int s0 = __shfl_sync(0xffffffffu, s, t);
            int s1 = __shfl_sync(0xffffffffu, s, t + 1);
            float wa0 = __shfl_sync(0xffffffffu, w0, t);
            float wb0 = __shfl_sync(0xffffffffu, w1, t);
            float wa1 = __shfl_sync(0xffffffffu, w0, t + 1);
            float wb1 = __shfl_sync(0xffffffffu, w1, t + 1);
            float we0 = head0 ? wa0 : wb0;
            float we1 = head0 ? wa1 : wb1;
            if (VEC == 4) {
                uint2 r0 = *(const uint2*)(hlane + (size_t)s0 * 2 * C);
                uint2 r1 = *(const uint2*)(hlane + (size_t)s1 * 2 * C);
                float2 f0 = __half22float2(*(__half2*)&r0.x);
                float2 f1 = __half22float2(*(__half2*)&r0.y);
                float2 g0 = __half22float2(*(__half2*)&r1.x);
                float2 g1 = __half22float2(*(__half2*)&r1.y);
                acc[0] = fmaf(we0, f0.x, acc[0]); acc[1] = fmaf(we0, f0.y, acc[1]);
                acc[2] = fmaf(we0, f1.x, acc[2]); acc[3] = fmaf(we0, f1.y, acc[3]);
                acc[0] = fmaf(we1, g0.x, acc[0]); acc[1] = fmaf(we1, g0.y, acc[1]);
                acc[2] = fmaf(we1, g1.x, acc[2]); acc[3] = fmaf(we1, g1.y, acc[3]);
            } else {
                unsigned r0 = *(const unsigned*)(hlane + (size_t)s0 * 2 * C);
                unsigned r1 = *(const unsigned*)(hlane + (size_t)s1 * 2 * C);
                float2 f0 = __half22float2(*(__half2*)&r0);
                float2 g0 = __half22float2(*(__half2*)&r1);
                acc[0] = fmaf(we0, f0.x, acc[0]); acc[1] = fmaf(we0, f0.y, acc[1]);
                acc[0] = fmaf(we1, g0.x, acc[0]); acc[1] = fmaf(we1, g0.y, acc[1]);
            }
        }
        if (t < cn) {
            int s0 = __shfl_sync(0xffffffffu, s, t);
            float wa0 = __shfl_sync(0xffffffffu, w0, t);
            float wb0 = __shfl_sync(0xffffffffu, w1, t);
            float we0 = head0 ? wa0 : wb0;
            if (VEC == 4) {
                uint2 r0 = *(const uint2*)(hlane + (size_t)s0 * 2 * C);
                float2 f0 = __half22float2(*(__half2*)&r0.x);
                float2 f1 = __half22float2(*(__half2*)&r0.y);
                acc[0] = fmaf(we0, f0.x, acc[0]); acc[1] = fmaf(we0, f0.y, acc[1]);
                acc[2] = fmaf(we0, f1.x, acc[2]); acc[3] = fmaf(we0, f1.y, acc[3]);
            } else {
                unsigned r0 = *(const unsigned*)(hlane + (size_t)s0 * 2 * C);
                float2 f0 = __half22float2(*(__half2*)&r0);
                acc[0] = fmaf(we0, f0.x, acc[0]); acc[1] = fmaf(we0, f0.y, acc[1]);
            }
        }
    }

#pragma unroll
    for (int off = 16; off >= 1; off >>= 1) {
        d0 += __shfl_xor_sync(0xffffffffu, d0, off);
        d1 += __shfl_xor_sync(0xffffffffu, d1, off);
    }
    float dm = (head0 ? d0 : d1) + 1e-16f;

    float res[VEC];
#pragma unroll
    for (int k = 0; k < VEC; k++) {
        float x = acc[k] / dm;
        float y = __shfl_xor_sync(0xffffffffu, x, 16);  // partner head value
        res[k] = 0.5f * (x + y);
    }
    if (head0) {
        int c0 = lane * VEC;
#pragma unroll
        for (int k = 0; k < VEC; k++) {
            float v = res[k] + bias[c0 + k];
            if (ELU) v = v > 0.f ? v : expm1f(v);
            res[k] = v;
        }
        float* op = out + (size_t)warp * C + c0;
        if (VEC == 4) *(float4*)op = make_float4(res[0], res[1], res[2], res[3]);
        else          *(float2*)op = make_float2(res[0], res[1]);
    }
}

// ---------------------------- launch ----------------------------
extern "C" void kernel_launch(void* const* d_in, const int* in_sizes, int n_in,
                              void* d_out, int out_size) {
    const float* x    = (const float*)d_in[0];
    const int*   ei   = (const int*)d_in[1];
    const float* W1   = (const float*)d_in[2];
    const float* as1w = (const float*)d_in[3];
    const float* ad1w = (const float*)d_in[4];
    const float* b1   = (const float*)d_in[5];
    const float* W2   = (const float*)d_in[6];
    const float* as2w = (const float*)d_in[7];
    const float* ad2w = (const float*)d_in[8];
    const float* b2   = (const float*)d_in[9];
    float* out = (float*)d_out;

    int N = in_sizes[0] / 128;
    int E = in_sizes[1] / 2;
    if (N > NMAX) N = NMAX;
    int Etot = E + N;

    __half *h1, *h2;
    float *hf;
    float2 *pas1, *pad1, *pas2, *pad2;
    int *counts, *offsets, *cursor, *adj, *bsums;
    cudaGetSymbolAddress((void**)&h1,     g_h1);
    cudaGetSymbolAddress((void**)&hf,     g_hf);
    cudaGetSymbolAddress((void**)&h2,     g_h2);
    cudaGetSymbolAddress((void**)&pas1,   g_as1);
    cudaGetSymbolAddress((void**)&pad1,   g_ad1);
    cudaGetSymbolAddress((void**)&pas2,   g_as2);
    cudaGetSymbolAddress((void**)&pad2,   g_ad2);
    cudaGetSymbolAddress((void**)&counts, g_counts);
    cudaGetSymbolAddress((void**)&offsets,g_offsets);
    cudaGetSymbolAddress((void**)&cursor, g_cursor);
    cudaGetSymbolAddress((void**)&adj,    g_adj);
    cudaGetSymbolAddress((void**)&bsums,  g_bsums);

    // GEMM1: K=128,M=128, KC=64, TM=8,TN=8 -> BM=128; smem 64KB(W)+32KB(A)=96KB -> 2 CTAs/SM
    const int SM1 = (128 * 128 + 128 * 64) * 4;   // 96 KB
    // GEMM2: K=64,M=64, KC=64, TM=8,TN=8 -> TXN=8,TYN=32,BM=256; smem 16KB+64KB=80KB -> 2 CTAs/SM
    const int SM2 = (64 * 64 + 256 * 64) * 4;     // 80 KB
    cudaFuncSetAttribute(gemm_attn_kernel<128, 128, 64, 8, 8>,
                         cudaFuncAttributeMaxDynamicSharedMemorySize, SM1);
    cudaFuncSetAttribute(gemm_attn_kernel<64, 64, 64, 8, 8>,
                         cudaFuncAttributeMaxDynamicSharedMemorySize, SM2);

    // ---- CSR build interleaved with layer-1 GEMM (GEMM at capture slot #3) ----
    zero_counts_kernel<<<(N + 255) / 256, 256>>>(counts, N);                     // 0
    count_kernel<<<(Etot + 255) / 256, 256>>>(ei, E, N, counts);                 // 1
    int nb = (N + 1023) / 1024;
    scan1_kernel<<<nb, 1024>>>(counts, offsets, bsums, N);                       // 2
    gemm_attn_kernel<128, 128, 64, 8, 8><<<(N + 127) / 128, 256, SM1>>>(         // 3
        x, W1, as1w, ad1w, h1, (float*)pas1, (float*)pad1, N);
    scan2_kernel<<<1, 128>>>(bsums, nb);                                         // 4
    scan3_kernel<<<(N + 255) / 256, 256>>>(offsets, bsums, counts, cursor, N);   // 5
    scatter_kernel<<<(Etot + 255) / 256, 256>>>(ei, E, N, cursor, adj);          // 6

    int warpGrid = (N * 32 + 255) / 256;
    aggregate_kernel<64, true><<<warpGrid, 256>>>(h1, pas1, pad1, offsets, adj, b1, hf, N);   // 7

    gemm_attn_kernel<64, 64, 64, 8, 8><<<(N + 255) / 256, 256, SM2>>>(           // 8
        hf, W2, as2w, ad2w, h2, (float*)pas2, (float*)pad2, N);
    aggregate_kernel<32, false><<<warpGrid, 256>>>(h2, pas2, pad2, offsets, adj, b2, out, N); // 9
}